// round 14
// baseline (speedup 1.0000x reference)
#include <cuda_runtime.h>
#include <cuda_bf16.h>
#include <mma.h>
#include <math.h>
#include <stdint.h>

using namespace nvcuda;

#define B 64
#define T 512
#define D 1024
#define RBLK 128          // recurrence grid: 32 n-splits x 4 b-splits

// ---------------- wx GEMM config (K-concat hi/lo, A converted in-kernel) ----------------
#define KK 3072
#define BM 128
#define BN 128
#define BK 32
#define NK (KK / BK)                 // 96
#define LDT 40                       // bf16 A/B smem row stride (elems)
#define AF_STRIDE 36                 // fp32 A stage row stride (floats)
#define AF_STAGE (128 * AF_STRIDE * 4)        // 18432 B
#define ABF_OFF (3 * AF_STAGE)                // 55296
#define ABF_STAGE (128 * LDT * 2)             // 10240 B
#define BB_OFF (ABF_OFF + 2 * ABF_STAGE)      // 75776
#define BB_STAGE (128 * LDT * 2)              // 10240 B
#define BIAS_OFF (BB_OFF + 3 * BB_STAGE)      // 106496
#define GEMM_SMEM (BIAS_OFF + 16 * BN * 4)    // 114688 B

// ---------------- recurrence smem config ----------------
#define ULD 1032                               // padded k-stride (bf16 elems)
#define U_ELEMS (32 * ULD)
#define H_ELEMS (16 * ULD)
#define U_REGION (2 * U_ELEMS * 2)             // dead after frag pinning
#define RNN_SMEM (U_REGION + 2 * H_ELEMS * 2)  // 198144 B

// ---------------- scratch ----------------
__device__ unsigned g_flags[4][32][8][8];              // per-(bi,ni,warp) step flags
__device__ __nv_bfloat16 g_ws[(size_t)D * KK];         // W split K-concat [hi|hi|lo]
__device__ __nv_bfloat16 g_hhi[2][B * D];              // h hi, double buffered
__device__ __nv_bfloat16 g_hlo[2][B * D];              // h lo
__device__ __nv_bfloat16 g_uhi[D * D];                 // U hi, row-major [n][k]
__device__ __nv_bfloat16 g_ulo[D * D];                 // U lo

// ---------------- helpers ----------------
__device__ __forceinline__ uint32_t smem_u32(const void* p) {
    uint32_t a;
    asm("{ .reg .u64 t; cvta.to.shared.u64 t, %1; cvt.u32.u64 %0, t; }" : "=r"(a) : "l"(p));
    return a;
}
__device__ __forceinline__ void cp_async16(uint32_t dst, const void* src) {
    asm volatile("cp.async.cg.shared.global [%0], [%1], 16;" :: "r"(dst), "l"(src) : "memory");
}
#define CP_COMMIT() asm volatile("cp.async.commit_group;" ::: "memory")

// ---------------- prep: split W (K-concat) + split U + zero h0/flags, ONE kernel ----------------
__global__ void prep(const float* __restrict__ W, const float* __restrict__ U) {
    size_t i = (size_t)blockIdx.x * blockDim.x + threadIdx.x;   // 0..262143 (D*D/4)

    // W split -> g_ws [hi|hi|lo]
    {
        float4 v = ((const float4*)W)[i];
        size_t e = i * 4, n = e >> 10;
        int k = (int)(e & 1023);
        __nv_bfloat16 hx = __float2bfloat16(v.x), hy = __float2bfloat16(v.y);
        __nv_bfloat16 hz = __float2bfloat16(v.z), hw = __float2bfloat16(v.w);
        __nv_bfloat162 h01(hx, hy), h23(hz, hw);
        __nv_bfloat162 l01(__float2bfloat16(v.x - __bfloat162float(hx)),
                           __float2bfloat16(v.y - __bfloat162float(hy)));
        __nv_bfloat162 l23(__float2bfloat16(v.z - __bfloat162float(hz)),
                           __float2bfloat16(v.w - __bfloat162float(hw)));
        __nv_bfloat16* row = g_ws + n * KK;
        *(__nv_bfloat162*)(row + k)       = h01;  *(__nv_bfloat162*)(row + k + 2)       = h23;
        *(__nv_bfloat162*)(row + D + k)   = h01;  *(__nv_bfloat162*)(row + D + k + 2)   = h23;
        *(__nv_bfloat162*)(row + 2*D + k) = l01;  *(__nv_bfloat162*)(row + 2*D + k + 2) = l23;
    }
    // U split -> g_uhi / g_ulo
    {
        float4 v = ((const float4*)U)[i];
        __nv_bfloat16 hx = __float2bfloat16(v.x), hy = __float2bfloat16(v.y);
        __nv_bfloat16 hz = __float2bfloat16(v.z), hw = __float2bfloat16(v.w);
        ((__nv_bfloat162*)g_uhi)[2*i]   = __nv_bfloat162(hx, hy);
        ((__nv_bfloat162*)g_uhi)[2*i+1] = __nv_bfloat162(hz, hw);
        ((__nv_bfloat162*)g_ulo)[2*i]   = __nv_bfloat162(__float2bfloat16(v.x - __bfloat162float(hx)),
                                                         __float2bfloat16(v.y - __bfloat162float(hy)));
        ((__nv_bfloat162*)g_ulo)[2*i+1] = __nv_bfloat162(__float2bfloat16(v.z - __bfloat162float(hz)),
                                                         __float2bfloat16(v.w - __bfloat162float(hw)));
    }
    // zero h0 (65536 bf16 per array = 8192 uint4) and flags (8192 u32 = 2048 uint4)
    uint4 z = make_uint4(0, 0, 0, 0);
    if (i < 8192) { ((uint4*)g_hhi[0])[i] = z; ((uint4*)g_hlo[0])[i] = z; }
    if (i < 2048) { ((uint4*)g_flags)[i] = z; }
}

// ================= wx = x @ W^T + Wb via wmma, x split fused in-kernel =================
__device__ __forceinline__ void fill_stage(uint32_t sb, int ks, int m0, int n0, int tid,
                                           const float* __restrict__ x) {
    const int st = ks % 3;
    // A: fp32 x tile, 128 rows x 32 floats (kk0 = (ks&31)*32; parts 0 and 2 reload same data)
    uint32_t sa = sb + st * AF_STAGE;
    const int kk0 = (ks & 31) * 32;
    #pragma unroll
    for (int j = 0; j < 4; ++j) {
        int idx = tid + j * 256;            // 0..1023
        int r = idx >> 3, c = idx & 7;      // row, 16B chunk (4 floats)
        cp_async16(sa + r * (AF_STRIDE * 4) + c * 16,
                   x + (size_t)(m0 + r) * D + kk0 + c * 4);
    }
    // B: bf16 from g_ws K-concat (unchanged)
    uint32_t sbb = sb + BB_OFF + st * BB_STAGE;
    #pragma unroll
    for (int j = 0; j < 2; ++j) {
        int idx = tid + j * 256;
        int r = idx >> 2, c = idx & 3;
        cp_async16(sbb + r * (LDT * 2) + c * 16, g_ws + (size_t)(n0 + r) * KK + ks * BK + c * 8);
    }
    CP_COMMIT();
}

__device__ __forceinline__ void convert_stage(char* smem, int st, int buf, bool is_lo, int tid) {
    const float* src = (const float*)(smem + st * AF_STAGE) + (tid >> 1) * AF_STRIDE + (tid & 1) * 16;
    __nv_bfloat16* dst = (__nv_bfloat16*)(smem + ABF_OFF + buf * ABF_STAGE)
                         + (tid >> 1) * LDT + (tid & 1) * 16;
    #pragma unroll
    for (int q = 0; q < 4; ++q) {
        float4 v = ((const float4*)src)[q];
        __nv_bfloat16 hx = __float2bfloat16(v.x), hy = __float2bfloat16(v.y);
        __nv_bfloat16 hz = __float2bfloat16(v.z), hw = __float2bfloat16(v.w);
        __nv_bfloat162 o01, o23;
        if (is_lo) {
            o01 = __nv_bfloat162(__float2bfloat16(v.x - __bfloat162float(hx)),
                                 __float2bfloat16(v.y - __bfloat162float(hy)));
            o23 = __nv_bfloat162(__float2bfloat16(v.z - __bfloat162float(hz)),
                                 __float2bfloat16(v.w - __bfloat162float(hw)));
        } else {
            o01 = __nv_bfloat162(hx, hy);
            o23 = __nv_bfloat162(hz, hw);
        }
        *(__nv_bfloat162*)(dst + q * 4)     = o01;
        *(__nv_bfloat162*)(dst + q * 4 + 2) = o23;
    }
}

__global__ void __launch_bounds__(256) gemm_wx_mma(float* __restrict__ out,
                                                   const float* __restrict__ x,
                                                   const float* __restrict__ Wb) {
    extern __shared__ char smem[];
    uint32_t sb = smem_u32(smem);
    float* biasT = (float*)(smem + BIAS_OFF);
    const int tid = threadIdx.x, warp = tid >> 5;
    const int wm = warp & 3, wn = warp >> 2;
    const int n0 = blockIdx.x * BN, m0 = blockIdx.y * BM;

    for (int i = tid; i < 16 * BN; i += 256) biasT[i] = Wb[n0 + (i & (BN - 1))];
    __syncthreads();

    wmma::fragment<wmma::accumulator, 16, 16, 16, float> c[2][4];
    #pragma unroll
    for (int i = 0; i < 2; ++i)
        #pragma unroll
        for (int j = 0; j < 4; ++j)
            wmma::load_matrix_sync(c[i][j], biasT + wn * 64 + j * 16, BN, wmma::mem_row_major);

    fill_stage(sb, 0, m0, n0, tid, x);
    fill_stage(sb, 1, m0, n0, tid, x);
    asm volatile("cp.async.wait_group 1;" ::: "memory");   // stage 0 arrived
    __syncthreads();
    convert_stage(smem, 0, 0, false, tid);                 // part 0 = hi

    for (int ks = 0; ks < NK; ++ks) {
        if (ks + 2 < NK) fill_stage(sb, ks + 2, m0, n0, tid, x);
        else CP_COMMIT();                                   // keep group accounting uniform
        asm volatile("cp.async.wait_group 1;" ::: "memory"); // stage ks+1 arrived
        __syncthreads();                                     // prev convert visible; buffers rotate

        // MMA on stage ks (A from bf16 buffer ks&1, B from stage ks%3)
        const __nv_bfloat16* As = (const __nv_bfloat16*)(smem + ABF_OFF + (ks & 1) * ABF_STAGE);
        const __nv_bfloat16* Bs = (const __nv_bfloat16*)(smem + BB_OFF + (ks % 3) * BB_STAGE);
        #pragma unroll
        for (int kk = 0; kk < 2; ++kk) {
            wmma::fragment<wmma::matrix_a, 16, 16, 16, __nv_bfloat16, wmma::row_major> a[2];
            wmma::fragment<wmma::matrix_b, 16, 16, 16, __nv_bfloat16, wmma::col_major> b[4];
            #pragma unroll
            for (int i = 0; i < 2; ++i)
                wmma::load_matrix_sync(a[i], As + (wm * 32 + i * 16) * LDT + kk * 16, LDT);
            #pragma unroll
            for (int j = 0; j < 4; ++j)
                wmma::load_matrix_sync(b[j], Bs + (wn * 64 + j * 16) * LDT + kk * 16, LDT);
            #pragma unroll
            for (int i = 0; i < 2; ++i)
                #pragma unroll
                for (int j = 0; j < 4; ++j)
                    wmma::mma_sync(c[i][j], a[i], b[j], c[i][j]);
        }

        // convert stage ks+1 (overlaps MMA in issue; consumed after next sync)
        if (ks + 1 < NK)
            convert_stage(smem, (ks + 1) % 3, (ks + 1) & 1, ((ks + 1) >> 5) == 1, tid);
    }

    #pragma unroll
    for (int i = 0; i < 2; ++i)
        #pragma unroll
        for (int j = 0; j < 4; ++j)
            wmma::store_matrix_sync(out + (size_t)(m0 + wm * 32 + i * 16) * D + n0 + wn * 64 + j * 16,
                                    c[i][j], D, wmma::mem_row_major);
}

// ================= persistent HMMA recurrence: EXACT R13 (proven) =================
__global__ void __launch_bounds__(256, 1) rnn_mma(float* __restrict__ out,
                                                  const float* __restrict__ Ub,
                                                  const float* __restrict__ bias) {
    extern __shared__ char sm[];
    __nv_bfloat16* s_uhi = (__nv_bfloat16*)sm;             // [32][ULD] (init only)
    __nv_bfloat16* s_ulo = s_uhi + U_ELEMS;
    __nv_bfloat16* s_hhi = (__nv_bfloat16*)(sm + U_REGION); // [16][ULD], warp-private slabs
    __nv_bfloat16* s_hlo = s_hhi + H_ELEMS;
    float* s_red = (float*)sm;                             // ALIAS of U region: [2][8][512]
    float* s_wx  = s_red + 2 * 8 * 512;                    // [3][512]

    const int tid = threadIdx.x, warp = tid >> 5, lane = tid & 31;
    const int ni = blockIdx.x >> 2, bi = blockIdx.x & 3;
    const int n0 = ni * 32, b0 = bi * 16;

    // ---- stage U slice once ----
    {
        uint32_t duh = smem_u32(s_uhi), dul = smem_u32(s_ulo);
        for (int i = tid; i < 32 * 128; i += 256) {
            int r = i >> 7, c = i & 127;
            cp_async16(duh + (r * ULD + c * 8) * 2, g_uhi + (size_t)(n0 + r) * D + c * 8);
            cp_async16(dul + (r * ULD + c * 8) * 2, g_ulo + (size_t)(n0 + r) * D + c * 8);
        }
        CP_COMMIT();
        asm volatile("cp.async.wait_group 0;" ::: "memory");
        __syncthreads();
    }

    const int kc0 = warp * 128;

    wmma::fragment<wmma::matrix_b, 16, 16, 16, __nv_bfloat16, wmma::col_major> pbh[8][2], pbl[8][2];
    #pragma unroll
    for (int ks = 0; ks < 8; ++ks) {
        const int kg = kc0 + ks * 16;
        #pragma unroll
        for (int j = 0; j < 2; ++j) {
            wmma::load_matrix_sync(pbh[ks][j], s_uhi + (size_t)(j * 16) * ULD + kg, ULD);
            wmma::load_matrix_sync(pbl[ks][j], s_ulo + (size_t)(j * 16) * ULD + kg, ULD);
        }
    }
    __syncthreads();   // U smem region may now be reused (s_red/s_wx alias)

    const uint32_t shh = smem_u32(s_hhi), shl = smem_u32(s_hlo);
    const uint32_t swx = smem_u32(s_wx);

    unsigned* myflag = &g_flags[bi][(warp << 2) + (lane >> 3)][lane & 7][0];
    unsigned* pubflag = &g_flags[bi][ni][warp][0];

    const int pr = tid >> 3, pc = tid & 7;
    const float* wx_src0 = out + (size_t)(b0 + pr) * (T * D) + n0 + pc * 4;
    const uint32_t wx_doff = (pr * 32 + pc * 4) * 4;

    const int eb  = tid >> 4;
    const int enl = (tid & 15) * 2;
    float2 cconst;
    cconst.x = Ub[n0 + enl]     + bias[n0 + enl];
    cconst.y = Ub[n0 + enl + 1] + bias[n0 + enl + 1];
    const size_t obase = (size_t)(b0 + eb) * (T * D) + n0 + enl;
    const int    hbase = (b0 + eb) * D + n0 + enl;
    const int    efr   = enl >> 4;
    const int    ec    = enl & 15;

    if (tid < 128) cp_async16(swx + wx_doff, wx_src0);
    CP_COMMIT();

    int wb = 0;
    for (int t = 0; t < T; ++t) {
        const __nv_bfloat16* Hhi = g_hhi[t & 1];
        const __nv_bfloat16* Hlo = g_hlo[t & 1];
        const int nwb = (wb == 2) ? 0 : wb + 1;

        {
            unsigned v;
            do {
                asm volatile("ld.acquire.gpu.global.u32 %0, [%1];" : "=r"(v) : "l"(myflag) : "memory");
            } while (v < (unsigned)t);
        }
        __syncwarp();

        #pragma unroll
        for (int j = 0; j < 8; ++j) {
            int i = lane + j * 32;
            int r = i >> 4, c = i & 15;
            uint32_t off = (r * ULD + kc0 + c * 8) * 2;
            const size_t goff = (size_t)(b0 + r) * D + kc0 + c * 8;
            cp_async16(shh + off, Hhi + goff);
            cp_async16(shl + off, Hlo + goff);
        }
        CP_COMMIT();

        if (t + 1 < T && tid < 128)
            cp_async16(swx + nwb * 2048 + wx_doff, wx_src0 + (size_t)(t + 1) * D);
        CP_COMMIT();

        asm volatile("cp.async.wait_group 1;" ::: "memory");
        __syncwarp();

        wmma::fragment<wmma::accumulator, 16, 16, 16, float> acc[2];
        wmma::fill_fragment(acc[0], 0.f);
        wmma::fill_fragment(acc[1], 0.f);
        #pragma unroll
        for (int ks = 0; ks < 8; ++ks) {
            const int kg = kc0 + ks * 16;
            wmma::fragment<wmma::matrix_a, 16, 16, 16, __nv_bfloat16, wmma::row_major> ah, al;
            wmma::load_matrix_sync(ah, s_hhi + kg, ULD);
            wmma::load_matrix_sync(al, s_hlo + kg, ULD);
            #pragma unroll
            for (int j = 0; j < 2; ++j) {
                wmma::mma_sync(acc[j], ah, pbh[ks][j], acc[j]);
                wmma::mma_sync(acc[j], al, pbh[ks][j], acc[j]);
                wmma::mma_sync(acc[j], ah, pbl[ks][j], acc[j]);
            }
        }
        float* red = s_red + (t & 1) * 4096;
        wmma::store_matrix_sync(red + warp * 512,       acc[0], 16, wmma::mem_row_major);
        wmma::store_matrix_sync(red + warp * 512 + 256, acc[1], 16, wmma::mem_row_major);
        __syncthreads();

        {
            const float* p = red + efr * 256 + eb * 16 + ec;
            float s0 = 0.f, s1 = 0.f;
            #pragma unroll
            for (int w = 0; w < 8; ++w) { s0 += p[w * 512]; s1 += p[w * 512 + 1]; }
            const float* wxp = s_wx + wb * 512 + eb * 32 + enl;
            float zx = tanhf(wxp[0] + s0 + cconst.x);
            float zy = tanhf(wxp[1] + s1 + cconst.y);

            __nv_bfloat16 hx = __float2bfloat16(zx), hy = __float2bfloat16(zy);
            *(__nv_bfloat162*)(g_hhi[(t + 1) & 1] + hbase) = __nv_bfloat162(hx, hy);
            *(__nv_bfloat162*)(g_hlo[(t + 1) & 1] + hbase) =
                __nv_bfloat162(__float2bfloat16(zx - __bfloat162float(hx)),
                               __float2bfloat16(zy - __bfloat162float(hy)));
            __syncwarp();
            if (lane == 0)
                asm volatile("st.release.gpu.global.u32 [%0], %1;"
                             :: "l"(pubflag), "r"((unsigned)(t + 1)) : "memory");

            *(float2*)(out + obase + (size_t)t * D) = make_float2(zx, zy);
            if (t == T - 1)
                *(float2*)(out + (size_t)B * T * D + hbase) = make_float2(zx, zy);
        }
        wb = nwb;
    }
}

extern "C" void kernel_launch(void* const* d_in, const int* in_sizes, int n_in,
                              void* d_out, int out_size) {
    const float* x    = (const float*)d_in[0];
    const float* Ww   = (const float*)d_in[1];
    const float* Wb   = (const float*)d_in[2];
    const float* Uw   = (const float*)d_in[3];
    const float* Ub   = (const float*)d_in[4];
    const float* bias = (const float*)d_in[5];
    float* out = (float*)d_out;

    cudaFuncSetAttribute(gemm_wx_mma, cudaFuncAttributeMaxDynamicSharedMemorySize, GEMM_SMEM);
    cudaFuncSetAttribute(rnn_mma,     cudaFuncAttributeMaxDynamicSharedMemorySize, RNN_SMEM);

    prep<<<D * D / 4 / 256, 256>>>(Ww, Uw);
    gemm_wx_mma<<<dim3(D / BN, (B * T) / BM), 256, GEMM_SMEM>>>(out, x, Wb);
    rnn_mma<<<RBLK, 256, RNN_SMEM>>>(out, Ub, bias);
}

// round 15
// speedup vs baseline: 1.0410x; 1.0410x over previous
#include <cuda_runtime.h>
#include <cuda_bf16.h>
#include <mma.h>
#include <math.h>
#include <stdint.h>

using namespace nvcuda;

#define B 64
#define T 512
#define D 1024
#define RBLK 128          // recurrence grid: 32 n-splits x 4 b-splits

// ---------------- wx GEMM config: K=1024, 32 chunks, 3 products/chunk ----------------
#define BM 128
#define BN 128
#define CK 32                         // K per chunk
#define NCH (D / CK)                  // 32 chunks
#define LDT 40                        // bf16 smem row stride (elems)
#define AF_STRIDE 36                  // fp32 A stage row stride (floats)
#define AF_STAGE (128 * AF_STRIDE * 4)        // 18432 B
#define ABF_OFF (3 * AF_STAGE)                // 55296  (A bf16: 2 bufs x (hi+lo))
#define ABF_BUF (2 * 128 * LDT * 2)           // 20480 B (hi+lo)
#define BB_OFF (ABF_OFF + 2 * ABF_BUF)        // 96256  (B bf16: 3 stages x (hi+lo))
#define BB_STAGE (2 * 128 * LDT * 2)          // 20480 B
#define BIAS_OFF (BB_OFF + 3 * BB_STAGE)      // 157696
#define GEMM_SMEM (BIAS_OFF + 16 * BN * 4)    // 165888 B

// ---------------- recurrence smem config ----------------
#define ULD 1032
#define U_ELEMS (32 * ULD)
#define H_ELEMS (16 * ULD)
#define U_REGION (2 * U_ELEMS * 2)
#define RNN_SMEM (U_REGION + 2 * H_ELEMS * 2)  // 198144 B

// ---------------- scratch ----------------
__device__ unsigned g_flags[4][32][8][8];
__device__ __nv_bfloat16 g_whi[(size_t)D * D];         // W hi, row-major [n][k]
__device__ __nv_bfloat16 g_wlo[(size_t)D * D];         // W lo
__device__ __nv_bfloat16 g_hhi[2][B * D];
__device__ __nv_bfloat16 g_hlo[2][B * D];
__device__ __nv_bfloat16 g_uhi[D * D];
__device__ __nv_bfloat16 g_ulo[D * D];

// ---------------- helpers ----------------
__device__ __forceinline__ uint32_t smem_u32(const void* p) {
    uint32_t a;
    asm("{ .reg .u64 t; cvta.to.shared.u64 t, %1; cvt.u32.u64 %0, t; }" : "=r"(a) : "l"(p));
    return a;
}
__device__ __forceinline__ void cp_async16(uint32_t dst, const void* src) {
    asm volatile("cp.async.cg.shared.global [%0], [%1], 16;" :: "r"(dst), "l"(src) : "memory");
}
#define CP_COMMIT() asm volatile("cp.async.commit_group;" ::: "memory")

// ---------------- prep: split W + U, zero h0/flags — ONE kernel ----------------
__global__ void prep(const float* __restrict__ W, const float* __restrict__ U) {
    size_t i = (size_t)blockIdx.x * blockDim.x + threadIdx.x;   // 0..262143 (D*D/4)
    {
        float4 v = ((const float4*)W)[i];
        __nv_bfloat16 hx = __float2bfloat16(v.x), hy = __float2bfloat16(v.y);
        __nv_bfloat16 hz = __float2bfloat16(v.z), hw = __float2bfloat16(v.w);
        ((__nv_bfloat162*)g_whi)[2*i]   = __nv_bfloat162(hx, hy);
        ((__nv_bfloat162*)g_whi)[2*i+1] = __nv_bfloat162(hz, hw);
        ((__nv_bfloat162*)g_wlo)[2*i]   = __nv_bfloat162(__float2bfloat16(v.x - __bfloat162float(hx)),
                                                         __float2bfloat16(v.y - __bfloat162float(hy)));
        ((__nv_bfloat162*)g_wlo)[2*i+1] = __nv_bfloat162(__float2bfloat16(v.z - __bfloat162float(hz)),
                                                         __float2bfloat16(v.w - __bfloat162float(hw)));
    }
    {
        float4 v = ((const float4*)U)[i];
        __nv_bfloat16 hx = __float2bfloat16(v.x), hy = __float2bfloat16(v.y);
        __nv_bfloat16 hz = __float2bfloat16(v.z), hw = __float2bfloat16(v.w);
        ((__nv_bfloat162*)g_uhi)[2*i]   = __nv_bfloat162(hx, hy);
        ((__nv_bfloat162*)g_uhi)[2*i+1] = __nv_bfloat162(hz, hw);
        ((__nv_bfloat162*)g_ulo)[2*i]   = __nv_bfloat162(__float2bfloat16(v.x - __bfloat162float(hx)),
                                                         __float2bfloat16(v.y - __bfloat162float(hy)));
        ((__nv_bfloat162*)g_ulo)[2*i+1] = __nv_bfloat162(__float2bfloat16(v.z - __bfloat162float(hz)),
                                                         __float2bfloat16(v.w - __bfloat162float(hw)));
    }
    uint4 z = make_uint4(0, 0, 0, 0);
    if (i < 8192) { ((uint4*)g_hhi[0])[i] = z; ((uint4*)g_hlo[0])[i] = z; }
    if (i < 2048) { ((uint4*)g_flags)[i] = z; }
}

// ================= wx = x @ W^T + Wb: fused split, K=1024, 3 products/chunk =================
__device__ __forceinline__ void fill_stage(uint32_t sb, int ks, int m0, int n0, int tid,
                                           const float* __restrict__ x) {
    const int st = ks % 3;
    // A: fp32 x chunk, 128 rows x 32 floats
    uint32_t sa = sb + st * AF_STAGE;
    #pragma unroll
    for (int j = 0; j < 4; ++j) {
        int idx = tid + j * 256;
        int r = idx >> 3, c = idx & 7;
        cp_async16(sa + r * (AF_STRIDE * 4) + c * 16, x + (size_t)(m0 + r) * D + ks * CK + c * 4);
    }
    // B hi + lo: 128 rows x 32 bf16 each
    uint32_t sbh = sb + BB_OFF + st * BB_STAGE;
    uint32_t sbl = sbh + 10240;
    #pragma unroll
    for (int j = 0; j < 2; ++j) {
        int idx = tid + j * 256;
        int r = idx >> 2, c = idx & 3;
        cp_async16(sbh + r * (LDT * 2) + c * 16, g_whi + (size_t)(n0 + r) * D + ks * CK + c * 8);
        cp_async16(sbl + r * (LDT * 2) + c * 16, g_wlo + (size_t)(n0 + r) * D + ks * CK + c * 8);
    }
    CP_COMMIT();
}

// convert fp32 stage st -> A_hi and A_lo in buffer buf (one pass, both outputs)
__device__ __forceinline__ void convert_stage(char* smem, int st, int buf, int tid) {
    const int row = tid >> 1, half = (tid & 1) * 16;
    const float* src = (const float*)(smem + st * AF_STAGE) + row * AF_STRIDE + half;
    __nv_bfloat16* dh = (__nv_bfloat16*)(smem + ABF_OFF + buf * ABF_BUF) + row * LDT + half;
    __nv_bfloat16* dl = dh + 5120;   // +10240 bytes
    #pragma unroll
    for (int q = 0; q < 4; ++q) {
        float4 v = ((const float4*)src)[q];
        __nv_bfloat16 hx = __float2bfloat16(v.x), hy = __float2bfloat16(v.y);
        __nv_bfloat16 hz = __float2bfloat16(v.z), hw = __float2bfloat16(v.w);
        *(__nv_bfloat162*)(dh + q * 4)     = __nv_bfloat162(hx, hy);
        *(__nv_bfloat162*)(dh + q * 4 + 2) = __nv_bfloat162(hz, hw);
        *(__nv_bfloat162*)(dl + q * 4)     = __nv_bfloat162(__float2bfloat16(v.x - __bfloat162float(hx)),
                                                            __float2bfloat16(v.y - __bfloat162float(hy)));
        *(__nv_bfloat162*)(dl + q * 4 + 2) = __nv_bfloat162(__float2bfloat16(v.z - __bfloat162float(hz)),
                                                            __float2bfloat16(v.w - __bfloat162float(hw)));
    }
}

__global__ void __launch_bounds__(256) gemm_wx_mma(float* __restrict__ out,
                                                   const float* __restrict__ x,
                                                   const float* __restrict__ Wb) {
    extern __shared__ char smem[];
    uint32_t sb = smem_u32(smem);
    float* biasT = (float*)(smem + BIAS_OFF);
    const int tid = threadIdx.x, warp = tid >> 5;
    const int wm = warp & 3, wn = warp >> 2;
    const int n0 = blockIdx.x * BN, m0 = blockIdx.y * BM;

    for (int i = tid; i < 16 * BN; i += 256) biasT[i] = Wb[n0 + (i & (BN - 1))];
    __syncthreads();

    wmma::fragment<wmma::accumulator, 16, 16, 16, float> c[2][4];
    #pragma unroll
    for (int i = 0; i < 2; ++i)
        #pragma unroll
        for (int j = 0; j < 4; ++j)
            wmma::load_matrix_sync(c[i][j], biasT + wn * 64 + j * 16, BN, wmma::mem_row_major);

    fill_stage(sb, 0, m0, n0, tid, x);
    fill_stage(sb, 1, m0, n0, tid, x);
    asm volatile("cp.async.wait_group 1;" ::: "memory");   // stage 0 arrived
    __syncthreads();
    convert_stage(smem, 0, 0, tid);

    for (int ks = 0; ks < NCH; ++ks) {
        if (ks + 2 < NCH) fill_stage(sb, ks + 2, m0, n0, tid, x);
        else CP_COMMIT();
        asm volatile("cp.async.wait_group 1;" ::: "memory"); // stage ks+1 arrived
        __syncthreads();                                     // prev convert visible

        const __nv_bfloat16* Ah = (const __nv_bfloat16*)(smem + ABF_OFF + (ks & 1) * ABF_BUF);
        const __nv_bfloat16* Al = Ah + 5120;
        const __nv_bfloat16* Bh = (const __nv_bfloat16*)(smem + BB_OFF + (ks % 3) * BB_STAGE);
        const __nv_bfloat16* Bl = Bh + 5120;
        #pragma unroll
        for (int kk = 0; kk < 2; ++kk) {
            wmma::fragment<wmma::matrix_a, 16, 16, 16, __nv_bfloat16, wmma::row_major> ah[2], al[2];
            #pragma unroll
            for (int i = 0; i < 2; ++i) {
                wmma::load_matrix_sync(ah[i], Ah + (wm * 32 + i * 16) * LDT + kk * 16, LDT);
                wmma::load_matrix_sync(al[i], Al + (wm * 32 + i * 16) * LDT + kk * 16, LDT);
            }
            #pragma unroll
            for (int j = 0; j < 4; ++j) {
                wmma::fragment<wmma::matrix_b, 16, 16, 16, __nv_bfloat16, wmma::col_major> bh, bl;
                wmma::load_matrix_sync(bh, Bh + (wn * 64 + j * 16) * LDT + kk * 16, LDT);
                wmma::load_matrix_sync(bl, Bl + (wn * 64 + j * 16) * LDT + kk * 16, LDT);
                #pragma unroll
                for (int i = 0; i < 2; ++i) {
                    wmma::mma_sync(c[i][j], ah[i], bh, c[i][j]);
                    wmma::mma_sync(c[i][j], al[i], bh, c[i][j]);
                    wmma::mma_sync(c[i][j], ah[i], bl, c[i][j]);
                }
            }
        }

        if (ks + 1 < NCH) convert_stage(smem, (ks + 1) % 3, (ks + 1) & 1, tid);
    }

    #pragma unroll
    for (int i = 0; i < 2; ++i)
        #pragma unroll
        for (int j = 0; j < 4; ++j)
            wmma::store_matrix_sync(out + (size_t)(m0 + wm * 32 + i * 16) * D + n0 + wn * 64 + j * 16,
                                    c[i][j], D, wmma::mem_row_major);
}

// ================= persistent HMMA recurrence: EXACT R13 (proven) =================
__global__ void __launch_bounds__(256, 1) rnn_mma(float* __restrict__ out,
                                                  const float* __restrict__ Ub,
                                                  const float* __restrict__ bias) {
    extern __shared__ char sm[];
    __nv_bfloat16* s_uhi = (__nv_bfloat16*)sm;
    __nv_bfloat16* s_ulo = s_uhi + U_ELEMS;
    __nv_bfloat16* s_hhi = (__nv_bfloat16*)(sm + U_REGION);
    __nv_bfloat16* s_hlo = s_hhi + H_ELEMS;
    float* s_red = (float*)sm;
    float* s_wx  = s_red + 2 * 8 * 512;

    const int tid = threadIdx.x, warp = tid >> 5, lane = tid & 31;
    const int ni = blockIdx.x >> 2, bi = blockIdx.x & 3;
    const int n0 = ni * 32, b0 = bi * 16;

    {
        uint32_t duh = smem_u32(s_uhi), dul = smem_u32(s_ulo);
        for (int i = tid; i < 32 * 128; i += 256) {
            int r = i >> 7, c = i & 127;
            cp_async16(duh + (r * ULD + c * 8) * 2, g_uhi + (size_t)(n0 + r) * D + c * 8);
            cp_async16(dul + (r * ULD + c * 8) * 2, g_ulo + (size_t)(n0 + r) * D + c * 8);
        }
        CP_COMMIT();
        asm volatile("cp.async.wait_group 0;" ::: "memory");
        __syncthreads();
    }

    const int kc0 = warp * 128;

    wmma::fragment<wmma::matrix_b, 16, 16, 16, __nv_bfloat16, wmma::col_major> pbh[8][2], pbl[8][2];
    #pragma unroll
    for (int ks = 0; ks < 8; ++ks) {
        const int kg = kc0 + ks * 16;
        #pragma unroll
        for (int j = 0; j < 2; ++j) {
            wmma::load_matrix_sync(pbh[ks][j], s_uhi + (size_t)(j * 16) * ULD + kg, ULD);
            wmma::load_matrix_sync(pbl[ks][j], s_ulo + (size_t)(j * 16) * ULD + kg, ULD);
        }
    }
    __syncthreads();

    const uint32_t shh = smem_u32(s_hhi), shl = smem_u32(s_hlo);
    const uint32_t swx = smem_u32(s_wx);

    unsigned* myflag = &g_flags[bi][(warp << 2) + (lane >> 3)][lane & 7][0];
    unsigned* pubflag = &g_flags[bi][ni][warp][0];

    const int pr = tid >> 3, pc = tid & 7;
    const float* wx_src0 = out + (size_t)(b0 + pr) * (T * D) + n0 + pc * 4;
    const uint32_t wx_doff = (pr * 32 + pc * 4) * 4;

    const int eb  = tid >> 4;
    const int enl = (tid & 15) * 2;
    float2 cconst;
    cconst.x = Ub[n0 + enl]     + bias[n0 + enl];
    cconst.y = Ub[n0 + enl + 1] + bias[n0 + enl + 1];
    const size_t obase = (size_t)(b0 + eb) * (T * D) + n0 + enl;
    const int    hbase = (b0 + eb) * D + n0 + enl;
    const int    efr   = enl >> 4;
    const int    ec    = enl & 15;

    if (tid < 128) cp_async16(swx + wx_doff, wx_src0);
    CP_COMMIT();

    int wb = 0;
    for (int t = 0; t < T; ++t) {
        const __nv_bfloat16* Hhi = g_hhi[t & 1];
        const __nv_bfloat16* Hlo = g_hlo[t & 1];
        const int nwb = (wb == 2) ? 0 : wb + 1;

        {
            unsigned v;
            do {
                asm volatile("ld.acquire.gpu.global.u32 %0, [%1];" : "=r"(v) : "l"(myflag) : "memory");
            } while (v < (unsigned)t);
        }
        __syncwarp();

        #pragma unroll
        for (int j = 0; j < 8; ++j) {
            int i = lane + j * 32;
            int r = i >> 4, c = i & 15;
            uint32_t off = (r * ULD + kc0 + c * 8) * 2;
            const size_t goff = (size_t)(b0 + r) * D + kc0 + c * 8;
            cp_async16(shh + off, Hhi + goff);
            cp_async16(shl + off, Hlo + goff);
        }
        CP_COMMIT();

        if (t + 1 < T && tid < 128)
            cp_async16(swx + nwb * 2048 + wx_doff, wx_src0 + (size_t)(t + 1) * D);
        CP_COMMIT();

        asm volatile("cp.async.wait_group 1;" ::: "memory");
        __syncwarp();

        wmma::fragment<wmma::accumulator, 16, 16, 16, float> acc[2];
        wmma::fill_fragment(acc[0], 0.f);
        wmma::fill_fragment(acc[1], 0.f);
        #pragma unroll
        for (int ks = 0; ks < 8; ++ks) {
            const int kg = kc0 + ks * 16;
            wmma::fragment<wmma::matrix_a, 16, 16, 16, __nv_bfloat16, wmma::row_major> ah, al;
            wmma::load_matrix_sync(ah, s_hhi + kg, ULD);
            wmma::load_matrix_sync(al, s_hlo + kg, ULD);
            #pragma unroll
            for (int j = 0; j < 2; ++j) {
                wmma::mma_sync(acc[j], ah, pbh[ks][j], acc[j]);
                wmma::mma_sync(acc[j], al, pbh[ks][j], acc[j]);
                wmma::mma_sync(acc[j], ah, pbl[ks][j], acc[j]);
            }
        }
        float* red = s_red + (t & 1) * 4096;
        wmma::store_matrix_sync(red + warp * 512,       acc[0], 16, wmma::mem_row_major);
        wmma::store_matrix_sync(red + warp * 512 + 256, acc[1], 16, wmma::mem_row_major);
        __syncthreads();

        {
            const float* p = red + efr * 256 + eb * 16 + ec;
            float s0 = 0.f, s1 = 0.f;
            #pragma unroll
            for (int w = 0; w < 8; ++w) { s0 += p[w * 512]; s1 += p[w * 512 + 1]; }
            const float* wxp = s_wx + wb * 512 + eb * 32 + enl;
            float zx = tanhf(wxp[0] + s0 + cconst.x);
            float zy = tanhf(wxp[1] + s1 + cconst.y);

            __nv_bfloat16 hx = __float2bfloat16(zx), hy = __float2bfloat16(zy);
            *(__nv_bfloat162*)(g_hhi[(t + 1) & 1] + hbase) = __nv_bfloat162(hx, hy);
            *(__nv_bfloat162*)(g_hlo[(t + 1) & 1] + hbase) =
                __nv_bfloat162(__float2bfloat16(zx - __bfloat162float(hx)),
                               __float2bfloat16(zy - __bfloat162float(hy)));
            __syncwarp();
            if (lane == 0)
                asm volatile("st.release.gpu.global.u32 [%0], %1;"
                             :: "l"(pubflag), "r"((unsigned)(t + 1)) : "memory");

            *(float2*)(out + obase + (size_t)t * D) = make_float2(zx, zy);
            if (t == T - 1)
                *(float2*)(out + (size_t)B * T * D + hbase) = make_float2(zx, zy);
        }
        wb = nwb;
    }
}

extern "C" void kernel_launch(void* const* d_in, const int* in_sizes, int n_in,
                              void* d_out, int out_size) {
    const float* x    = (const float*)d_in[0];
    const float* Ww   = (const float*)d_in[1];
    const float* Wb   = (const float*)d_in[2];
    const float* Uw   = (const float*)d_in[3];
    const float* Ub   = (const float*)d_in[4];
    const float* bias = (const float*)d_in[5];
    float* out = (float*)d_out;

    cudaFuncSetAttribute(gemm_wx_mma, cudaFuncAttributeMaxDynamicSharedMemorySize, GEMM_SMEM);
    cudaFuncSetAttribute(rnn_mma,     cudaFuncAttributeMaxDynamicSharedMemorySize, RNN_SMEM);

    prep<<<D * D / 4 / 256, 256>>>(Ww, Uw);
    gemm_wx_mma<<<dim3(D / BN, (B * T) / BM), 256, GEMM_SMEM>>>(out, x, Wb);
    rnn_mma<<<RBLK, 256, RNN_SMEM>>>(out, Ub, bias);
}

// round 16
// speedup vs baseline: 1.0477x; 1.0064x over previous
#include <cuda_runtime.h>
#include <cuda_bf16.h>
#include <mma.h>
#include <math.h>
#include <stdint.h>

using namespace nvcuda;

#define B 64
#define T 512
#define D 1024
#define RBLK 128          // recurrence grid: 32 n-splits x 4 b-splits

// ---------------- wx GEMM config (K-concat hi/lo trick, K'=3072, BK=64) ----------------
#define KK 3072
#define BM 128
#define BN 128
#define BK 64
#define NK (KK / BK)                          // 48
#define LDT 72                                // padded smem row stride (elems): 64 + 8
#define STAGE_A (BM * LDT * 2)                // 18432 B
#define AB_STAGES 3
#define SMEM_B_OFF (AB_STAGES * STAGE_A)      // 55296
#define SMEM_BIAS_OFF (2 * AB_STAGES * STAGE_A)   // 110592
#define GEMM_SMEM (SMEM_BIAS_OFF + 16 * BN * 4)   // 118784

// ---------------- recurrence smem config ----------------
#define ULD 1032                               // padded k-stride (bf16 elems)
#define U_ELEMS (32 * ULD)
#define H_ELEMS (16 * ULD)
#define U_REGION (2 * U_ELEMS * 2)             // dead after frag pinning
#define RNN_SMEM (U_REGION + 2 * H_ELEMS * 2)  // 198144 B

// ---------------- scratch ----------------
__device__ unsigned g_flags[4][32][8][8];              // per-(bi,ni,warp) step flags
__device__ __nv_bfloat16 g_xs[(size_t)B * T * KK];     // x split K-concat [hi|lo|hi]
__device__ __nv_bfloat16 g_ws[(size_t)D * KK];         // W split K-concat [hi|hi|lo]
__device__ __nv_bfloat16 g_hhi[2][B * D];              // h hi, double buffered
__device__ __nv_bfloat16 g_hlo[2][B * D];              // h lo
__device__ __nv_bfloat16 g_uhi[D * D];                 // U hi, row-major [n][k]
__device__ __nv_bfloat16 g_ulo[D * D];                 // U lo

// ---------------- helpers ----------------
__device__ __forceinline__ uint32_t smem_u32(const void* p) {
    uint32_t a;
    asm("{ .reg .u64 t; cvta.to.shared.u64 t, %1; cvt.u32.u64 %0, t; }" : "=r"(a) : "l"(p));
    return a;
}
__device__ __forceinline__ void cp_async16(uint32_t dst, const void* src) {
    asm volatile("cp.async.cg.shared.global [%0], [%1], 16;" :: "r"(dst), "l"(src) : "memory");
}
#define CP_COMMIT() asm volatile("cp.async.commit_group;" ::: "memory")

// ---------------- init: zero h0 and the exchange flags ----------------
__global__ void zero_h0() {
    int i = blockIdx.x * blockDim.x + threadIdx.x;
    if (i < B * D) {
        g_hhi[0][i] = __nv_bfloat16(0.f);
        g_hlo[0][i] = __nv_bfloat16(0.f);
    }
    if (i < 4 * 32 * 8) g_flags[i >> 8][(i >> 3) & 31][i & 7][0] = 0;
}

// ---------------- fp32 -> bf16 splits ----------------
__global__ void split_x(const float* __restrict__ s) {
    size_t i = (size_t)blockIdx.x * blockDim.x + threadIdx.x;
    float4 v = ((const float4*)s)[i];
    size_t e = i * 4;
    size_t m = e >> 10;
    int    k = (int)(e & 1023);
    __nv_bfloat16 hx = __float2bfloat16(v.x), hy = __float2bfloat16(v.y);
    __nv_bfloat16 hz = __float2bfloat16(v.z), hw = __float2bfloat16(v.w);
    __nv_bfloat162 h01(hx, hy), h23(hz, hw);
    __nv_bfloat162 l01(__float2bfloat16(v.x - __bfloat162float(hx)),
                       __float2bfloat16(v.y - __bfloat162float(hy)));
    __nv_bfloat162 l23(__float2bfloat16(v.z - __bfloat162float(hz)),
                       __float2bfloat16(v.w - __bfloat162float(hw)));
    __nv_bfloat16* row = g_xs + m * KK;
    *(__nv_bfloat162*)(row + k)       = h01;  *(__nv_bfloat162*)(row + k + 2)       = h23;
    *(__nv_bfloat162*)(row + D + k)   = l01;  *(__nv_bfloat162*)(row + D + k + 2)   = l23;
    *(__nv_bfloat162*)(row + 2*D + k) = h01;  *(__nv_bfloat162*)(row + 2*D + k + 2) = h23;
}
__global__ void split_w(const float* __restrict__ s) {
    size_t i = (size_t)blockIdx.x * blockDim.x + threadIdx.x;
    float4 v = ((const float4*)s)[i];
    size_t e = i * 4;
    size_t n = e >> 10;
    int    k = (int)(e & 1023);
    __nv_bfloat16 hx = __float2bfloat16(v.x), hy = __float2bfloat16(v.y);
    __nv_bfloat16 hz = __float2bfloat16(v.z), hw = __float2bfloat16(v.w);
    __nv_bfloat162 h01(hx, hy), h23(hz, hw);
    __nv_bfloat162 l01(__float2bfloat16(v.x - __bfloat162float(hx)),
                       __float2bfloat16(v.y - __bfloat162float(hy)));
    __nv_bfloat162 l23(__float2bfloat16(v.z - __bfloat162float(hz)),
                       __float2bfloat16(v.w - __bfloat162float(hw)));
    __nv_bfloat16* row = g_ws + n * KK;
    *(__nv_bfloat162*)(row + k)       = h01;  *(__nv_bfloat162*)(row + k + 2)       = h23;
    *(__nv_bfloat162*)(row + D + k)   = h01;  *(__nv_bfloat162*)(row + D + k + 2)   = h23;
    *(__nv_bfloat162*)(row + 2*D + k) = l01;  *(__nv_bfloat162*)(row + 2*D + k + 2) = l23;
}
__global__ void split_U(const float* __restrict__ s) {
    size_t i = (size_t)blockIdx.x * blockDim.x + threadIdx.x;
    float4 v = ((const float4*)s)[i];
    __nv_bfloat16 hx = __float2bfloat16(v.x), hy = __float2bfloat16(v.y);
    __nv_bfloat16 hz = __float2bfloat16(v.z), hw = __float2bfloat16(v.w);
    ((__nv_bfloat162*)g_uhi)[2*i]   = __nv_bfloat162(hx, hy);
    ((__nv_bfloat162*)g_uhi)[2*i+1] = __nv_bfloat162(hz, hw);
    ((__nv_bfloat162*)g_ulo)[2*i]   = __nv_bfloat162(__float2bfloat16(v.x - __bfloat162float(hx)),
                                                     __float2bfloat16(v.y - __bfloat162float(hy)));
    ((__nv_bfloat162*)g_ulo)[2*i+1] = __nv_bfloat162(__float2bfloat16(v.z - __bfloat162float(hz)),
                                                     __float2bfloat16(v.w - __bfloat162float(hw)));
}

// ================= wx = x @ W^T + Wb via wmma, BK=64 (48 iterations) =================
__device__ __forceinline__ void fill_stage(uint32_t sb, int s, int m0, int n0, int k0, int tid) {
    uint32_t sa = sb + s * STAGE_A;
    uint32_t sbb = sb + SMEM_B_OFF + s * STAGE_A;
    #pragma unroll
    for (int j = 0; j < 4; ++j) {
        int idx = tid + j * 256;           // 0..1023
        int r = idx >> 3, c = idx & 7;     // row 0..127, 16B chunk 0..7
        cp_async16(sa + r * (LDT * 2) + c * 16, g_xs + (size_t)(m0 + r) * KK + k0 + c * 8);
    }
    #pragma unroll
    for (int j = 0; j < 4; ++j) {
        int idx = tid + j * 256;
        int r = idx >> 3, c = idx & 7;
        cp_async16(sbb + r * (LDT * 2) + c * 16, g_ws + (size_t)(n0 + r) * KK + k0 + c * 8);
    }
    CP_COMMIT();
}

__global__ void __launch_bounds__(256) gemm_wx_mma(float* __restrict__ out,
                                                   const float* __restrict__ Wb) {
    extern __shared__ char smem[];
    uint32_t sb = smem_u32(smem);
    float* biasT = (float*)(smem + SMEM_BIAS_OFF);
    const int tid = threadIdx.x, warp = tid >> 5;
    const int wm = warp & 3, wn = warp >> 2;
    const int n0 = blockIdx.x * BN, m0 = blockIdx.y * BM;

    for (int i = tid; i < 16 * BN; i += 256) biasT[i] = Wb[n0 + (i & (BN - 1))];
    __syncthreads();

    wmma::fragment<wmma::accumulator, 16, 16, 16, float> c[2][4];
    #pragma unroll
    for (int i = 0; i < 2; ++i)
        #pragma unroll
        for (int j = 0; j < 4; ++j)
            wmma::load_matrix_sync(c[i][j], biasT + wn * 64 + j * 16, BN, wmma::mem_row_major);

    fill_stage(sb, 0, m0, n0, 0, tid);
    fill_stage(sb, 1, m0, n0, BK, tid);

    int rs = 0, ws = 2;
    for (int ks = 0; ks < NK; ++ks) {
        asm volatile("cp.async.wait_group 1;" ::: "memory");
        __syncthreads();

        const __nv_bfloat16* As = (const __nv_bfloat16*)(smem + rs * STAGE_A);
        const __nv_bfloat16* Bs = (const __nv_bfloat16*)(smem + SMEM_B_OFF + rs * STAGE_A);
        #pragma unroll
        for (int kk = 0; kk < 4; ++kk) {
            wmma::fragment<wmma::matrix_a, 16, 16, 16, __nv_bfloat16, wmma::row_major> a[2];
            wmma::fragment<wmma::matrix_b, 16, 16, 16, __nv_bfloat16, wmma::col_major> b[4];
            #pragma unroll
            for (int i = 0; i < 2; ++i)
                wmma::load_matrix_sync(a[i], As + (wm * 32 + i * 16) * LDT + kk * 16, LDT);
            #pragma unroll
            for (int j = 0; j < 4; ++j)
                wmma::load_matrix_sync(b[j], Bs + (wn * 64 + j * 16) * LDT + kk * 16, LDT);
            #pragma unroll
            for (int i = 0; i < 2; ++i)
                #pragma unroll
                for (int j = 0; j < 4; ++j)
                    wmma::mma_sync(c[i][j], a[i], b[j], c[i][j]);
        }

        if (ks + 2 < NK) fill_stage(sb, ws, m0, n0, (ks + 2) * BK, tid);
        else CP_COMMIT();
        rs = (rs == 2) ? 0 : rs + 1;
        ws = (ws == 2) ? 0 : ws + 1;
    }

    #pragma unroll
    for (int i = 0; i < 2; ++i)
        #pragma unroll
        for (int j = 0; j < 4; ++j)
            wmma::store_matrix_sync(out + (size_t)(m0 + wm * 32 + i * 16) * D + n0 + wn * 64 + j * 16,
                                    c[i][j], D, wmma::mem_row_major);
}

// ================= persistent HMMA recurrence: EXACT R13 (proven) =================
__global__ void __launch_bounds__(256, 1) rnn_mma(float* __restrict__ out,
                                                  const float* __restrict__ Ub,
                                                  const float* __restrict__ bias) {
    extern __shared__ char sm[];
    __nv_bfloat16* s_uhi = (__nv_bfloat16*)sm;             // [32][ULD] (init only)
    __nv_bfloat16* s_ulo = s_uhi + U_ELEMS;
    __nv_bfloat16* s_hhi = (__nv_bfloat16*)(sm + U_REGION); // [16][ULD], warp-private slabs
    __nv_bfloat16* s_hlo = s_hhi + H_ELEMS;
    float* s_red = (float*)sm;                             // ALIAS of U region: [2][8][512]
    float* s_wx  = s_red + 2 * 8 * 512;                    // [3][512]

    const int tid = threadIdx.x, warp = tid >> 5, lane = tid & 31;
    const int ni = blockIdx.x >> 2, bi = blockIdx.x & 3;
    const int n0 = ni * 32, b0 = bi * 16;

    {
        uint32_t duh = smem_u32(s_uhi), dul = smem_u32(s_ulo);
        for (int i = tid; i < 32 * 128; i += 256) {
            int r = i >> 7, c = i & 127;
            cp_async16(duh + (r * ULD + c * 8) * 2, g_uhi + (size_t)(n0 + r) * D + c * 8);
            cp_async16(dul + (r * ULD + c * 8) * 2, g_ulo + (size_t)(n0 + r) * D + c * 8);
        }
        CP_COMMIT();
        asm volatile("cp.async.wait_group 0;" ::: "memory");
        __syncthreads();
    }

    const int kc0 = warp * 128;

    wmma::fragment<wmma::matrix_b, 16, 16, 16, __nv_bfloat16, wmma::col_major> pbh[8][2], pbl[8][2];
    #pragma unroll
    for (int ks = 0; ks < 8; ++ks) {
        const int kg = kc0 + ks * 16;
        #pragma unroll
        for (int j = 0; j < 2; ++j) {
            wmma::load_matrix_sync(pbh[ks][j], s_uhi + (size_t)(j * 16) * ULD + kg, ULD);
            wmma::load_matrix_sync(pbl[ks][j], s_ulo + (size_t)(j * 16) * ULD + kg, ULD);
        }
    }
    __syncthreads();   // U smem region may now be reused (s_red/s_wx alias)

    const uint32_t shh = smem_u32(s_hhi), shl = smem_u32(s_hlo);
    const uint32_t swx = smem_u32(s_wx);

    unsigned* myflag = &g_flags[bi][(warp << 2) + (lane >> 3)][lane & 7][0];
    unsigned* pubflag = &g_flags[bi][ni][warp][0];

    const int pr = tid >> 3, pc = tid & 7;
    const float* wx_src0 = out + (size_t)(b0 + pr) * (T * D) + n0 + pc * 4;
    const uint32_t wx_doff = (pr * 32 + pc * 4) * 4;

    const int eb  = tid >> 4;
    const int enl = (tid & 15) * 2;
    float2 cconst;
    cconst.x = Ub[n0 + enl]     + bias[n0 + enl];
    cconst.y = Ub[n0 + enl + 1] + bias[n0 + enl + 1];
    const size_t obase = (size_t)(b0 + eb) * (T * D) + n0 + enl;
    const int    hbase = (b0 + eb) * D + n0 + enl;
    const int    efr   = enl >> 4;
    const int    ec    = enl & 15;

    if (tid < 128) cp_async16(swx + wx_doff, wx_src0);
    CP_COMMIT();

    int wb = 0;
    for (int t = 0; t < T; ++t) {
        const __nv_bfloat16* Hhi = g_hhi[t & 1];
        const __nv_bfloat16* Hlo = g_hlo[t & 1];
        const int nwb = (wb == 2) ? 0 : wb + 1;

        {
            unsigned v;
            do {
                asm volatile("ld.acquire.gpu.global.u32 %0, [%1];" : "=r"(v) : "l"(myflag) : "memory");
            } while (v < (unsigned)t);
        }
        __syncwarp();

        #pragma unroll
        for (int j = 0; j < 8; ++j) {
            int i = lane + j * 32;
            int r = i >> 4, c = i & 15;
            uint32_t off = (r * ULD + kc0 + c * 8) * 2;
            const size_t goff = (size_t)(b0 + r) * D + kc0 + c * 8;
            cp_async16(shh + off, Hhi + goff);
            cp_async16(shl + off, Hlo + goff);
        }
        CP_COMMIT();

        if (t + 1 < T && tid < 128)
            cp_async16(swx + nwb * 2048 + wx_doff, wx_src0 + (size_t)(t + 1) * D);
        CP_COMMIT();

        asm volatile("cp.async.wait_group 1;" ::: "memory");
        __syncwarp();

        wmma::fragment<wmma::accumulator, 16, 16, 16, float> acc[2];
        wmma::fill_fragment(acc[0], 0.f);
        wmma::fill_fragment(acc[1], 0.f);
        #pragma unroll
        for (int ks = 0; ks < 8; ++ks) {
            const int kg = kc0 + ks * 16;
            wmma::fragment<wmma::matrix_a, 16, 16, 16, __nv_bfloat16, wmma::row_major> ah, al;
            wmma::load_matrix_sync(ah, s_hhi + kg, ULD);
            wmma::load_matrix_sync(al, s_hlo + kg, ULD);
            #pragma unroll
            for (int j = 0; j < 2; ++j) {
                wmma::mma_sync(acc[j], ah, pbh[ks][j], acc[j]);
                wmma::mma_sync(acc[j], al, pbh[ks][j], acc[j]);
                wmma::mma_sync(acc[j], ah, pbl[ks][j], acc[j]);
            }
        }
        float* red = s_red + (t & 1) * 4096;
        wmma::store_matrix_sync(red + warp * 512,       acc[0], 16, wmma::mem_row_major);
        wmma::store_matrix_sync(red + warp * 512 + 256, acc[1], 16, wmma::mem_row_major);
        __syncthreads();

        {
            const float* p = red + efr * 256 + eb * 16 + ec;
            float s0 = 0.f, s1 = 0.f;
            #pragma unroll
            for (int w = 0; w < 8; ++w) { s0 += p[w * 512]; s1 += p[w * 512 + 1]; }
            const float* wxp = s_wx + wb * 512 + eb * 32 + enl;
            float zx = tanhf(wxp[0] + s0 + cconst.x);
            float zy = tanhf(wxp[1] + s1 + cconst.y);

            __nv_bfloat16 hx = __float2bfloat16(zx), hy = __float2bfloat16(zy);
            *(__nv_bfloat162*)(g_hhi[(t + 1) & 1] + hbase) = __nv_bfloat162(hx, hy);
            *(__nv_bfloat162*)(g_hlo[(t + 1) & 1] + hbase) =
                __nv_bfloat162(__float2bfloat16(zx - __bfloat162float(hx)),
                               __float2bfloat16(zy - __bfloat162float(hy)));
            __syncwarp();
            if (lane == 0)
                asm volatile("st.release.gpu.global.u32 [%0], %1;"
                             :: "l"(pubflag), "r"((unsigned)(t + 1)) : "memory");

            *(float2*)(out + obase + (size_t)t * D) = make_float2(zx, zy);
            if (t == T - 1)
                *(float2*)(out + (size_t)B * T * D + hbase) = make_float2(zx, zy);
        }
        wb = nwb;
    }
}

extern "C" void kernel_launch(void* const* d_in, const int* in_sizes, int n_in,
                              void* d_out, int out_size) {
    const float* x    = (const float*)d_in[0];
    const float* Ww   = (const float*)d_in[1];
    const float* Wb   = (const float*)d_in[2];
    const float* Uw   = (const float*)d_in[3];
    const float* Ub   = (const float*)d_in[4];
    const float* bias = (const float*)d_in[5];
    float* out = (float*)d_out;

    cudaFuncSetAttribute(gemm_wx_mma, cudaFuncAttributeMaxDynamicSharedMemorySize, GEMM_SMEM);
    cudaFuncSetAttribute(rnn_mma,     cudaFuncAttributeMaxDynamicSharedMemorySize, RNN_SMEM);

    zero_h0<<<(B * D + 255) / 256, 256>>>();
    split_x<<<((size_t)B * T * D / 4) / 256, 256>>>(x);
    split_w<<<(D * D / 4) / 256, 256>>>(Ww);
    split_U<<<(D * D / 4) / 256, 256>>>(Uw);
    gemm_wx_mma<<<dim3(D / BN, (B * T) / BM), 256, GEMM_SMEM>>>(out, Wb);
    rnn_mma<<<RBLK, 256, RNN_SMEM>>>(out, Ub, bias);
}